// round 13
// baseline (speedup 1.0000x reference)
#include <cuda_runtime.h>
#include <cuda_fp16.h>
#include <cstdint>
#include <cstddef>

#define M_Q    256
#define N_X    50000
#define DIM    3072
#define KCONST 750.0f
#define TOPK   16
#define NCAND  24

#define TILE_N  128
#define N_TILES 391              // ceil(50000/128)
#define KC      64               // k-chunk (elements)
#define CHUNKS  48               // 3072/64
#define A_STAGE    32768         // 256 rows x 128 B (f16), x3
#define BF32_STAGE 32768         // 128 rows x 256 B (fp32), x2
#define OFF_BF32 (3*A_STAGE)                  // 98304
#define OFF_BH   (OFF_BF32 + 2*BF32_STAGE)    // 163840 (f16 B tile x2)
#define OFF_CT   (OFF_BH + 2*16384)           // 196608
#define OFF_BSQ  (OFF_CT + 512)               // 197120
#define SMEM_TOTAL (OFF_BSQ + 1024)           // 198144

#define INF_F __int_as_float(0x7f800000)
typedef unsigned long long u64;

// ---------------- device scratch ----------------
__device__ float  g_wmax;
__device__ __half g_Xth[M_Q * DIM];            // f16 copy of X_tilde only
__device__ float  g_ct[N_X];                   // exact |X_j|^2 + w'_j^2
__device__ u64    g_cand1[(size_t)M_Q * N_TILES * 4];  // per-tile top-4/row, 3.2MB
__device__ int    g_cand2[M_Q * NCAND];        // final candidate indices

// ---------------- helpers ----------------
__device__ __forceinline__ uint32_t h2_bits(__half2 h) {
    return *reinterpret_cast<uint32_t*>(&h);
}
__device__ __forceinline__ uint32_t smem_u32(const void* p) {
    uint32_t a;
    asm("{ .reg .u64 t; cvta.to.shared.u64 t, %1; cvt.u32.u64 %0, t; }" : "=r"(a) : "l"(p));
    return a;
}
__device__ __forceinline__ void cp16(uint32_t dst, const void* src) {
    asm volatile("cp.async.cg.shared.global [%0], [%1], 16;"
                 :: "r"(dst), "l"(src) : "memory");
}
#define CP_COMMIT() asm volatile("cp.async.commit_group;" ::: "memory")
#define CP_WAIT1()  asm volatile("cp.async.wait_group 1;" ::: "memory")
#define CP_WAIT0()  asm volatile("cp.async.wait_group 0;" ::: "memory")

#define LDMATRIX_X4(r0, r1, r2, r3, addr)                                     \
    asm volatile("ldmatrix.sync.aligned.m8n8.x4.shared.b16 {%0,%1,%2,%3}, [%4];" \
                 : "=r"(r0), "=r"(r1), "=r"(r2), "=r"(r3) : "r"(addr))

#define MMA_F16(d, a, b)                                                       \
    asm volatile("mma.sync.aligned.m16n8k16.row.col.f32.f16.f16.f32 "          \
                 "{%0,%1,%2,%3}, {%4,%5,%6,%7}, {%8,%9}, {%0,%1,%2,%3};"       \
                 : "+f"((d)[0]), "+f"((d)[1]), "+f"((d)[2]), "+f"((d)[3])      \
                 : "r"((a)[0]), "r"((a)[1]), "r"((a)[2]), "r"((a)[3]),         \
                   "r"((b)[0]), "r"((b)[1]))

__device__ __forceinline__ u64 umin64(u64 a, u64 b) { return a < b ? a : b; }
__device__ __forceinline__ u64 umax64(u64 a, u64 b) { return a > b ? a : b; }

// insert key into ascending 4-list t0..t3
#define INS4(k) do {                                                           \
    if ((k) < t3) {                                                            \
        if ((k) < t2) {                                                        \
            t3 = t2;                                                           \
            if ((k) < t1) {                                                    \
                t2 = t1;                                                       \
                if ((k) < t0) { t1 = t0; t0 = (k); } else t1 = (k);            \
            } else t2 = (k);                                                   \
        } else t3 = (k);                                                       \
    }                                                                          \
} while (0)

// merge my ascending 4-list with xor-lane partner's, keep bottom 4 (bitonic)
#define MERGE4_XOR(mask) do {                                                  \
    const u64 b0 = __shfl_xor_sync(0xffffffffu, t0, (mask));                   \
    const u64 b1 = __shfl_xor_sync(0xffffffffu, t1, (mask));                   \
    const u64 b2 = __shfl_xor_sync(0xffffffffu, t2, (mask));                   \
    const u64 b3 = __shfl_xor_sync(0xffffffffu, t3, (mask));                   \
    const u64 l0 = umin64(t0, b3), l1 = umin64(t1, b2);                        \
    const u64 l2 = umin64(t2, b1), l3 = umin64(t3, b0);                        \
    const u64 m0 = umin64(l0, l2), m2 = umax64(l0, l2);                        \
    const u64 m1 = umin64(l1, l3), m3 = umax64(l1, l3);                        \
    t0 = umin64(m0, m1); t1 = umax64(m0, m1);                                  \
    t2 = umin64(m2, m3); t3 = umax64(m2, m3);                                  \
} while (0)

// ---------------- kernel 0: convert X_tilde + max(w) (merged) --------------
__global__ __launch_bounds__(256) void k_cvtw(
    const float* __restrict__ Xt, const float* __restrict__ w)
{
    if (blockIdx.x == 32) {      // wmax block
        __shared__ float sm[256];
        float v = -INF_F;
        for (int i = threadIdx.x; i < N_X; i += 256) v = fmaxf(v, w[i]);
        sm[threadIdx.x] = v;
        __syncthreads();
        for (int s = 128; s > 0; s >>= 1) {
            if (threadIdx.x < s) sm[threadIdx.x] = fmaxf(sm[threadIdx.x], sm[threadIdx.x + s]);
            __syncthreads();
        }
        if (threadIdx.x == 0) g_wmax = sm[0];
        return;
    }
    const int warp = blockIdx.x * 8 + (threadIdx.x >> 5);   // 0..255
    const int lane = threadIdx.x & 31;
    const float4* src = (const float4*)(Xt + (size_t)warp * DIM);
    uint4* dst = (uint4*)(g_Xth + (size_t)warp * DIM);
#pragma unroll 4
    for (int i = lane; i < DIM / 8; i += 32) {
        const float4 v0 = src[2*i], v1 = src[2*i + 1];
        uint4 o;
        o.x = h2_bits(__floats2half2_rn(v0.x, v0.y));
        o.y = h2_bits(__floats2half2_rn(v0.z, v0.w));
        o.z = h2_bits(__floats2half2_rn(v1.x, v1.y));
        o.w = h2_bits(__floats2half2_rn(v1.z, v1.w));
        dst[i] = o;
    }
}

// ---------------- kernel 1: fused f16 GEMM + in-tile top-4 selection -------
__device__ __forceinline__ void issueAB(uint32_t sb, int c,
                                        const float* __restrict__ X,
                                        int n0, int tid)
{
    const int k0 = c * KC;
    const uint32_t ab = sb + (c % 3) * A_STAGE;
    const uint32_t bb = sb + OFF_BF32 + (c & 1) * BF32_STAGE;
#pragma unroll
    for (int i = 0; i < 8; i++) {                 // A: 2048 16B units (f16)
        const int uid = tid + 256 * i;
        const int row = uid >> 3, u = uid & 7;
        cp16(ab + row * 128 + ((u ^ (row & 7)) << 4),
             g_Xth + (size_t)row * DIM + k0 + u * 8);
    }
#pragma unroll
    for (int i = 0; i < 8; i++) {                 // B: 2048 16B units (fp32)
        const int uid = tid + 256 * i;
        const int row = uid >> 4, u = uid & 15;
        const int gj  = n0 + row;
        cp16(bb + row * 256 + ((u ^ (row & 15)) << 4),
             X + (size_t)(gj < N_X ? gj : N_X - 1) * DIM + k0 + u * 4);
    }
}

__global__ __launch_bounds__(256, 1) void k_score(
    const float* __restrict__ X, const float* __restrict__ w)
{
    extern __shared__ char smem[];
    const uint32_t sb = smem_u32(smem);
    const int tid  = threadIdx.x;
    const int wid  = tid >> 5;
    const int lane = tid & 31;
    const int qr   = lane >> 2;
    const int qc   = lane & 3;
    const int wm   = wid >> 1;
    const int wn   = wid & 1;
    const int n0   = blockIdx.x * TILE_N;

    const int brow  = tid >> 1;
    const int bhalf = tid & 1;
    uint32_t ld_off[8], sts_off[4];
#pragma unroll
    for (int u = 0; u < 8; u++)
        ld_off[u] = brow * 256 + (((bhalf * 8 + u) ^ (brow & 15)) << 4);
#pragma unroll
    for (int q = 0; q < 4; q++)
        sts_off[q] = brow * 128 + (((bhalf * 4 + q) ^ (brow & 7)) << 4);

    const int sel = lane >> 3;
    const int rl  = lane & 7;
    const int rA  = ((sel & 1) << 3) + rl;
    const int uA  = sel >> 1;
    const int rB  = ((sel >> 1) << 3) + rl;
    const int uB  = sel & 1;

    float bsq = 0.f;

#define CONVERT(cc) do {                                                       \
        const char* bf = smem + OFF_BF32 + ((cc) & 1) * BF32_STAGE;            \
        char* bh = smem + OFF_BH + ((cc) & 1) * 16384;                         \
        _Pragma("unroll")                                                      \
        for (int q = 0; q < 4; q++) {                                          \
            const float4 v0 = *(const float4*)(bf + ld_off[2*q]);              \
            const float4 v1 = *(const float4*)(bf + ld_off[2*q + 1]);          \
            bsq = fmaf(v0.x, v0.x, fmaf(v0.y, v0.y,                            \
                  fmaf(v0.z, v0.z, fmaf(v0.w, v0.w, bsq))));                   \
            bsq = fmaf(v1.x, v1.x, fmaf(v1.y, v1.y,                            \
                  fmaf(v1.z, v1.z, fmaf(v1.w, v1.w, bsq))));                   \
            uint4 o;                                                           \
            o.x = h2_bits(__floats2half2_rn(v0.x, v0.y));                      \
            o.y = h2_bits(__floats2half2_rn(v0.z, v0.w));                      \
            o.z = h2_bits(__floats2half2_rn(v1.x, v1.y));                      \
            o.w = h2_bits(__floats2half2_rn(v1.z, v1.w));                      \
            *(uint4*)(bh + sts_off[q]) = o;                                    \
        }                                                                      \
    } while (0)

    issueAB(sb, 0, X, n0, tid); CP_COMMIT();
    issueAB(sb, 1, X, n0, tid); CP_COMMIT();
    CP_WAIT1();
    __syncthreads();
    CONVERT(0);

    float acc[4][8][4];
#pragma unroll
    for (int mt = 0; mt < 4; mt++)
#pragma unroll
        for (int nt = 0; nt < 8; nt++)
#pragma unroll
            for (int q = 0; q < 4; q++) acc[mt][nt][q] = 0.f;

    for (int c = 0; c < CHUNKS; c++) {
        CP_WAIT0();
        __syncthreads();

        if (c + 1 < CHUNKS) CONVERT(c + 1);          // overlaps with MMA(c)
        if (c + 2 < CHUNKS) { issueAB(sb, c + 2, X, n0, tid); CP_COMMIT(); }

        const uint32_t Ab = sb + (c % 3) * A_STAGE;
        const uint32_t Bb = sb + OFF_BH + (c & 1) * 16384;
#pragma unroll
        for (int ks = 0; ks < 4; ks++) {
            uint32_t a[4][4], b[8][2];
#pragma unroll
            for (int mt = 0; mt < 4; mt++) {
                const int row = wm * 64 + mt * 16 + rA;
                const uint32_t addr = Ab + row * 128 + (((ks*2 + uA) ^ rl) << 4);
                LDMATRIX_X4(a[mt][0], a[mt][1], a[mt][2], a[mt][3], addr);
            }
#pragma unroll
            for (int p = 0; p < 4; p++) {
                const int row = wn * 64 + p * 16 + rB;
                const uint32_t addr = Bb + row * 128 + (((ks*2 + uB) ^ rl) << 4);
                LDMATRIX_X4(b[2*p][0], b[2*p][1], b[2*p+1][0], b[2*p+1][1], addr);
            }
#pragma unroll
            for (int mt = 0; mt < 4; mt++)
#pragma unroll
                for (int nt = 0; nt < 8; nt++)
                    MMA_F16(acc[mt][nt], a[mt], b[nt]);
        }
    }
#undef CONVERT

    // ---- exact column terms ----
    float* bsqs = (float*)(smem + OFF_BSQ);
    float* cts  = (float*)(smem + OFF_CT);
    __syncthreads();                 // mainloop smem reads complete
    bsqs[tid] = bsq;
    __syncthreads();
    if (tid < TILE_N) {
        const int j = n0 + tid;
        float v = INF_F;
        if (j < N_X) {
            const float wp = (g_wmax - w[j]) * (1.f / KCONST);
            v = bsqs[2*tid] + bsqs[2*tid + 1] + wp * wp;
            g_ct[j] = v;
        }
        cts[tid] = v;                // INF for padded cols -> never selected
    }
    __syncthreads();

    // ---- in-tile per-row top-4 selection (replaces score writes) ----
    // key = (score_bits << 32) | global_idx (scores positive -> bit order ok)
    u64* selb = (u64*)smem;          // 256 rows x 8 keys = 16KB (A stages dead)

#pragma unroll
    for (int mt = 0; mt < 4; mt++) {
#pragma unroll
        for (int half = 0; half < 2; half++) {
            u64 t0 = ~0ull, t1 = ~0ull, t2 = ~0ull, t3 = ~0ull;
#pragma unroll
            for (int nt = 0; nt < 8; nt++) {
#pragma unroll
                for (int e = 0; e < 2; e++) {
                    const int col = wn * 64 + nt * 8 + 2 * qc + e;
                    const float s = cts[col] - 2.f * acc[mt][nt][half * 2 + e];
                    const u64 key = ((u64)__float_as_uint(s) << 32)
                                  | (unsigned)(n0 + col);
                    INS4(key);
                }
            }
            MERGE4_XOR(1);           // combine qc pairs
            MERGE4_XOR(2);           // combine qc quads
            if (qc == 0) {
                const int row = wm * 64 + mt * 16 + half * 8 + qr;
                u64* d = selb + row * 8 + wn * 4;
                d[0] = t0; d[1] = t1; d[2] = t2; d[3] = t3;
            }
        }
    }
    __syncthreads();

    // final cross-warp merge: one thread per row, write tile top-4 to global
    if (tid < 256) {
        const u64* s = selb + tid * 8;
        const u64 a0 = s[0], a1 = s[1], a2 = s[2], a3 = s[3];
        const u64 b0 = s[4], b1 = s[5], b2 = s[6], b3 = s[7];
        const u64 l0 = umin64(a0, b3), l1 = umin64(a1, b2);
        const u64 l2 = umin64(a2, b1), l3 = umin64(a3, b0);
        const u64 m0 = umin64(l0, l2), m2 = umax64(l0, l2);
        const u64 m1 = umin64(l1, l3), m3 = umax64(l1, l3);
        u64* d = g_cand1 + ((size_t)tid * N_TILES + blockIdx.x) * 4;
        d[0] = umin64(m0, m1); d[1] = umax64(m0, m1);
        d[2] = umin64(m2, m3); d[3] = umax64(m2, m3);
    }
}

// ---------------- kernel 2: per-row top-24 from 1564 tile candidates -------
__global__ __launch_bounds__(256) void k_sel()
{
    __shared__ u64 buf[128];
    const int row  = blockIdx.x;
    const int tid  = threadIdx.x;
    const int warp = tid >> 5;
    const int lane = tid & 31;
    const u64* keys = g_cand1 + (size_t)row * (N_TILES * 4);

    u64 t0 = ~0ull, t1 = ~0ull, t2 = ~0ull, t3 = ~0ull;
    for (int i = tid; i < N_TILES * 4; i += 256) {
        const u64 k = keys[i];
        INS4(k);
    }

    // warp top-16 extraction
    u64 mine = ~0ull;
#pragma unroll
    for (int r = 0; r < 16; r++) {
        u64 k = t0;
#pragma unroll
        for (int o = 16; o > 0; o >>= 1)
            k = umin64(k, __shfl_xor_sync(0xffffffffu, k, o));
        if (lane == r) mine = k;
        if (k == t0) { t0 = t1; t1 = t2; t2 = t3; t3 = ~0ull; }
    }
    if (lane < 16) buf[warp * 16 + lane] = mine;
    __syncthreads();

    // rank-select top-NCAND of 128
    if (tid < 128) {
        const u64 v = buf[tid];
        int rk = 0;
        for (int o = 0; o < 128; o++) rk += (buf[o] < v);
        if (rk < NCAND) g_cand2[row * NCAND + rk] = (int)(unsigned)(v & 0xffffffffu);
    }
}

// ---------------- kernel 3: exact rerank + L1 + max -------------------------
// 768 threads = 24 warps: one warp per candidate (single gather pass).
__global__ __launch_bounds__(768) void k_post(
    const float* __restrict__ Xt, const float* __restrict__ X,
    const float* __restrict__ w, float* __restrict__ out)
{
    __shared__ int   cand[NCAND];
    __shared__ float xts[DIM];
    __shared__ float d2s[NCAND];
    __shared__ float acts[NCAND];

    const int row  = blockIdx.x;
    const int tid  = threadIdx.x;
    const int warp = tid >> 5;
    const int lane = tid & 31;

    if (tid < NCAND) cand[tid] = g_cand2[row * NCAND + tid];

    const float4* xtg = (const float4*)(Xt + (size_t)row * DIM);
    for (int i = tid; i < DIM / 4; i += 768) ((float4*)xts)[i] = xtg[i];
    __syncthreads();

    if (warp < NCAND) {
        const int j = cand[warp];
        const float4* xj  = (const float4*)(X + (size_t)j * DIM);
        const float4* xt4 = (const float4*)xts;
        float dot = 0.f, l1 = 0.f;
#pragma unroll 4
        for (int i = lane; i < DIM / 4; i += 32) {
            const float4 a = xj[i], b = xt4[i];
            dot = fmaf(a.x, b.x, fmaf(a.y, b.y, fmaf(a.z, b.z, fmaf(a.w, b.w, dot))));
            l1 += fabsf(a.x-b.x) + fabsf(a.y-b.y) + fabsf(a.z-b.z) + fabsf(a.w-b.w);
        }
#pragma unroll
        for (int o = 16; o > 0; o >>= 1) {
            dot += __shfl_xor_sync(0xffffffffu, dot, o);
            l1  += __shfl_xor_sync(0xffffffffu, l1,  o);
        }
        if (lane == 0) {
            d2s[warp]  = g_ct[j] - 2.f * dot;
            acts[warp] = w[j] - KCONST * l1;
        }
    }
    __syncthreads();

    // exact top-16 by d2 (reference tie-break), max activation among them
    if (tid < 32) {
        const float v = (tid < NCAND) ? d2s[tid] : INF_F;
        const int   j = (tid < NCAND) ? cand[tid] : 0x7fffffff;
        int rank = 0;
#pragma unroll
        for (int o = 0; o < 32; o++) {
            const float ov = __shfl_sync(0xffffffffu, v, o);
            const int   oj = __shfl_sync(0xffffffffu, j, o);
            rank += (ov < v || (ov == v && oj < j)) ? 1 : 0;
        }
        float a = (rank < TOPK && tid < NCAND) ? acts[tid] : -INF_F;
#pragma unroll
        for (int o = 16; o > 0; o >>= 1) a = fmaxf(a, __shfl_xor_sync(0xffffffffu, a, o));
        if (tid == 0) out[row] = a;
    }
}

// ---------------------------------------------------------------------------
extern "C" void kernel_launch(void* const* d_in, const int* in_sizes, int n_in,
                              void* d_out, int out_size)
{
    const float* Xt = (const float*)d_in[0];
    const float* X  = (const float*)d_in[1];
    const float* w  = (const float*)d_in[2];
    float* out = (float*)d_out;

    cudaFuncSetAttribute(k_score, cudaFuncAttributeMaxDynamicSharedMemorySize,
                         SMEM_TOTAL);

    k_cvtw<<<33, 256>>>(Xt, w);
    k_score<<<N_TILES, 256, SMEM_TOTAL>>>(X, w);
    k_sel<<<M_Q, 256>>>();
    k_post<<<M_Q, 768>>>(Xt, X, w, out);
}

// round 14
// speedup vs baseline: 1.1033x; 1.1033x over previous
#include <cuda_runtime.h>
#include <cuda_fp16.h>
#include <cstdint>
#include <cstddef>

#define M_Q    256
#define N_X    50000
#define DIM    3072
#define KCONST 750.0f
#define TOPK   16
#define NCAND  24

#define TILE_N  128
#define N_TILES 391              // ceil(50000/128)
#define KC      64               // k-chunk (elements)
#define CHUNKS  48               // 3072/64
#define A_STAGE    32768         // 256 rows x 128 B (f16), x3
#define BF32_STAGE 32768         // 128 rows x 256 B (fp32), x2
#define OFF_BF32 (3*A_STAGE)                  // 98304
#define OFF_BH   (OFF_BF32 + 2*BF32_STAGE)    // 163840 (f16 B tile x2)
#define OFF_CT   (OFF_BH + 2*16384)           // 196608
#define OFF_BSQ  (OFF_CT + 512)               // 197120
#define SMEM_TOTAL (OFF_BSQ + 1024)           // 198144

#define INF_F __int_as_float(0x7f800000)
typedef unsigned long long u64;

// ---------------- device scratch ----------------
__device__ float    g_wmax;
__device__ __half   g_Xth[M_Q * DIM];          // f16 copy of X_tilde only
__device__ float    g_ct[N_X];                 // exact |X_j|^2 + w'_j^2
__device__ uint32_t g_cand1[(size_t)M_Q * N_TILES * 4];  // per-tile top-4 keys
__device__ int      g_cand2[M_Q * NCAND];      // final candidate indices

// ---------------- helpers ----------------
__device__ __forceinline__ uint32_t h2_bits(__half2 h) {
    return *reinterpret_cast<uint32_t*>(&h);
}
__device__ __forceinline__ uint32_t smem_u32(const void* p) {
    uint32_t a;
    asm("{ .reg .u64 t; cvta.to.shared.u64 t, %1; cvt.u32.u64 %0, t; }" : "=r"(a) : "l"(p));
    return a;
}
__device__ __forceinline__ void cp16(uint32_t dst, const void* src) {
    asm volatile("cp.async.cg.shared.global [%0], [%1], 16;"
                 :: "r"(dst), "l"(src) : "memory");
}
#define CP_COMMIT() asm volatile("cp.async.commit_group;" ::: "memory")
#define CP_WAIT1()  asm volatile("cp.async.wait_group 1;" ::: "memory")
#define CP_WAIT0()  asm volatile("cp.async.wait_group 0;" ::: "memory")

#define LDMATRIX_X4(r0, r1, r2, r3, addr)                                     \
    asm volatile("ldmatrix.sync.aligned.m8n8.x4.shared.b16 {%0,%1,%2,%3}, [%4];" \
                 : "=r"(r0), "=r"(r1), "=r"(r2), "=r"(r3) : "r"(addr))

#define MMA_F16(d, a, b)                                                       \
    asm volatile("mma.sync.aligned.m16n8k16.row.col.f32.f16.f16.f32 "          \
                 "{%0,%1,%2,%3}, {%4,%5,%6,%7}, {%8,%9}, {%0,%1,%2,%3};"       \
                 : "+f"((d)[0]), "+f"((d)[1]), "+f"((d)[2]), "+f"((d)[3])      \
                 : "r"((a)[0]), "r"((a)[1]), "r"((a)[2]), "r"((a)[3]),         \
                   "r"((b)[0]), "r"((b)[1]))

__device__ __forceinline__ u64 umin64(u64 a, u64 b) { return a < b ? a : b; }
__device__ __forceinline__ u64 umax64(u64 a, u64 b) { return a > b ? a : b; }

// branch-free insert of u32 key into ascending 4-list t0..t3 (7 VMNMX)
#define INS4_U32(k) do {                                                       \
    uint32_t _c = (k), _n;                                                     \
    _n = min(t0, _c); _c = max(t0, _c); t0 = _n;                               \
    _n = min(t1, _c); _c = max(t1, _c); t1 = _n;                               \
    _n = min(t2, _c); _c = max(t2, _c); t2 = _n;                               \
    t3 = min(t3, _c);                                                          \
} while (0)

// branch-free insert of u64 key into ascending 4-list t0..t3
#define INS4_U64(k) do {                                                       \
    u64 _c = (k), _n;                                                          \
    _n = umin64(t0, _c); _c = umax64(t0, _c); t0 = _n;                         \
    _n = umin64(t1, _c); _c = umax64(t1, _c); t1 = _n;                         \
    _n = umin64(t2, _c); _c = umax64(t2, _c); t2 = _n;                         \
    t3 = umin64(t3, _c);                                                       \
} while (0)

// merge my ascending u32 4-list with xor-lane partner's, keep bottom 4
#define MERGE4_XOR32(mask) do {                                                \
    const uint32_t b0 = __shfl_xor_sync(0xffffffffu, t0, (mask));              \
    const uint32_t b1 = __shfl_xor_sync(0xffffffffu, t1, (mask));              \
    const uint32_t b2 = __shfl_xor_sync(0xffffffffu, t2, (mask));              \
    const uint32_t b3 = __shfl_xor_sync(0xffffffffu, t3, (mask));              \
    const uint32_t l0 = min(t0, b3), l1 = min(t1, b2);                         \
    const uint32_t l2 = min(t2, b1), l3 = min(t3, b0);                         \
    const uint32_t m0 = min(l0, l2), m2 = max(l0, l2);                         \
    const uint32_t m1 = min(l1, l3), m3 = max(l1, l3);                         \
    t0 = min(m0, m1); t1 = max(m0, m1);                                        \
    t2 = min(m2, m3); t3 = max(m2, m3);                                        \
} while (0)

// ---------------- kernel 0: convert X_tilde + max(w) (merged) --------------
__global__ __launch_bounds__(256) void k_cvtw(
    const float* __restrict__ Xt, const float* __restrict__ w)
{
    if (blockIdx.x == 32) {      // wmax block
        __shared__ float sm[256];
        float v = -INF_F;
        for (int i = threadIdx.x; i < N_X; i += 256) v = fmaxf(v, w[i]);
        sm[threadIdx.x] = v;
        __syncthreads();
        for (int s = 128; s > 0; s >>= 1) {
            if (threadIdx.x < s) sm[threadIdx.x] = fmaxf(sm[threadIdx.x], sm[threadIdx.x + s]);
            __syncthreads();
        }
        if (threadIdx.x == 0) g_wmax = sm[0];
        return;
    }
    const int warp = blockIdx.x * 8 + (threadIdx.x >> 5);   // 0..255
    const int lane = threadIdx.x & 31;
    const float4* src = (const float4*)(Xt + (size_t)warp * DIM);
    uint4* dst = (uint4*)(g_Xth + (size_t)warp * DIM);
#pragma unroll 4
    for (int i = lane; i < DIM / 8; i += 32) {
        const float4 v0 = src[2*i], v1 = src[2*i + 1];
        uint4 o;
        o.x = h2_bits(__floats2half2_rn(v0.x, v0.y));
        o.y = h2_bits(__floats2half2_rn(v0.z, v0.w));
        o.z = h2_bits(__floats2half2_rn(v1.x, v1.y));
        o.w = h2_bits(__floats2half2_rn(v1.z, v1.w));
        dst[i] = o;
    }
}

// ---------------- kernel 1: fused f16 GEMM + branch-free top-4 selection ---
__device__ __forceinline__ void issueAB(uint32_t sb, int c,
                                        const float* __restrict__ X,
                                        int n0, int tid)
{
    const int k0 = c * KC;
    const uint32_t ab = sb + (c % 3) * A_STAGE;
    const uint32_t bb = sb + OFF_BF32 + (c & 1) * BF32_STAGE;
#pragma unroll
    for (int i = 0; i < 8; i++) {                 // A: 2048 16B units (f16)
        const int uid = tid + 256 * i;
        const int row = uid >> 3, u = uid & 7;
        cp16(ab + row * 128 + ((u ^ (row & 7)) << 4),
             g_Xth + (size_t)row * DIM + k0 + u * 8);
    }
#pragma unroll
    for (int i = 0; i < 8; i++) {                 // B: 2048 16B units (fp32)
        const int uid = tid + 256 * i;
        const int row = uid >> 4, u = uid & 15;
        const int gj  = n0 + row;
        cp16(bb + row * 256 + ((u ^ (row & 15)) << 4),
             X + (size_t)(gj < N_X ? gj : N_X - 1) * DIM + k0 + u * 4);
    }
}

__global__ __launch_bounds__(256, 1) void k_score(
    const float* __restrict__ X, const float* __restrict__ w)
{
    extern __shared__ char smem[];
    const uint32_t sb = smem_u32(smem);
    const int tid  = threadIdx.x;
    const int wid  = tid >> 5;
    const int lane = tid & 31;
    const int qr   = lane >> 2;
    const int qc   = lane & 3;
    const int wm   = wid >> 1;
    const int wn   = wid & 1;
    const int n0   = blockIdx.x * TILE_N;

    const int brow  = tid >> 1;
    const int bhalf = tid & 1;
    uint32_t ld_off[8], sts_off[4];
#pragma unroll
    for (int u = 0; u < 8; u++)
        ld_off[u] = brow * 256 + (((bhalf * 8 + u) ^ (brow & 15)) << 4);
#pragma unroll
    for (int q = 0; q < 4; q++)
        sts_off[q] = brow * 128 + (((bhalf * 4 + q) ^ (brow & 7)) << 4);

    const int sel = lane >> 3;
    const int rl  = lane & 7;
    const int rA  = ((sel & 1) << 3) + rl;
    const int uA  = sel >> 1;
    const int rB  = ((sel >> 1) << 3) + rl;
    const int uB  = sel & 1;

    float bsq = 0.f;

#define CONVERT(cc) do {                                                       \
        const char* bf = smem + OFF_BF32 + ((cc) & 1) * BF32_STAGE;            \
        char* bh = smem + OFF_BH + ((cc) & 1) * 16384;                         \
        _Pragma("unroll")                                                      \
        for (int q = 0; q < 4; q++) {                                          \
            const float4 v0 = *(const float4*)(bf + ld_off[2*q]);              \
            const float4 v1 = *(const float4*)(bf + ld_off[2*q + 1]);          \
            bsq = fmaf(v0.x, v0.x, fmaf(v0.y, v0.y,                            \
                  fmaf(v0.z, v0.z, fmaf(v0.w, v0.w, bsq))));                   \
            bsq = fmaf(v1.x, v1.x, fmaf(v1.y, v1.y,                            \
                  fmaf(v1.z, v1.z, fmaf(v1.w, v1.w, bsq))));                   \
            uint4 o;                                                           \
            o.x = h2_bits(__floats2half2_rn(v0.x, v0.y));                      \
            o.y = h2_bits(__floats2half2_rn(v0.z, v0.w));                      \
            o.z = h2_bits(__floats2half2_rn(v1.x, v1.y));                      \
            o.w = h2_bits(__floats2half2_rn(v1.z, v1.w));                      \
            *(uint4*)(bh + sts_off[q]) = o;                                    \
        }                                                                      \
    } while (0)

    issueAB(sb, 0, X, n0, tid); CP_COMMIT();
    issueAB(sb, 1, X, n0, tid); CP_COMMIT();
    CP_WAIT1();
    __syncthreads();
    CONVERT(0);

    float acc[4][8][4];
#pragma unroll
    for (int mt = 0; mt < 4; mt++)
#pragma unroll
        for (int nt = 0; nt < 8; nt++)
#pragma unroll
            for (int q = 0; q < 4; q++) acc[mt][nt][q] = 0.f;

    for (int c = 0; c < CHUNKS; c++) {
        CP_WAIT0();
        __syncthreads();

        if (c + 1 < CHUNKS) CONVERT(c + 1);          // overlaps with MMA(c)
        if (c + 2 < CHUNKS) { issueAB(sb, c + 2, X, n0, tid); CP_COMMIT(); }

        const uint32_t Ab = sb + (c % 3) * A_STAGE;
        const uint32_t Bb = sb + OFF_BH + (c & 1) * 16384;
#pragma unroll
        for (int ks = 0; ks < 4; ks++) {
            uint32_t a[4][4], b[8][2];
#pragma unroll
            for (int mt = 0; mt < 4; mt++) {
                const int row = wm * 64 + mt * 16 + rA;
                const uint32_t addr = Ab + row * 128 + (((ks*2 + uA) ^ rl) << 4);
                LDMATRIX_X4(a[mt][0], a[mt][1], a[mt][2], a[mt][3], addr);
            }
#pragma unroll
            for (int p = 0; p < 4; p++) {
                const int row = wn * 64 + p * 16 + rB;
                const uint32_t addr = Bb + row * 128 + (((ks*2 + uB) ^ rl) << 4);
                LDMATRIX_X4(b[2*p][0], b[2*p][1], b[2*p+1][0], b[2*p+1][1], addr);
            }
#pragma unroll
            for (int mt = 0; mt < 4; mt++)
#pragma unroll
                for (int nt = 0; nt < 8; nt++)
                    MMA_F16(acc[mt][nt], a[mt], b[nt]);
        }
    }
#undef CONVERT

    // ---- exact column terms ----
    float* bsqs = (float*)(smem + OFF_BSQ);
    float* cts  = (float*)(smem + OFF_CT);
    __syncthreads();                 // mainloop smem reads complete
    bsqs[tid] = bsq;
    __syncthreads();
    if (tid < TILE_N) {
        const int j = n0 + tid;
        float v = INF_F;
        if (j < N_X) {
            const float wp = (g_wmax - w[j]) * (1.f / KCONST);
            v = bsqs[2*tid] + bsqs[2*tid + 1] + wp * wp;
            g_ct[j] = v;
        }
        cts[tid] = v;                // INF for padded cols -> never selected
    }
    __syncthreads();

    // ---- in-tile per-row top-4 selection (branch-free, u32 keys) ----
    // key = (score_bits & ~0x7F) | tile_col. Score positive; 7-bit truncation
    // (~0.06 abs) << f16 matmul noise; col makes keys unique within the tile.
    float ctr[16];
#pragma unroll
    for (int nt = 0; nt < 8; nt++) {
        ctr[2*nt]     = cts[wn * 64 + nt * 8 + 2 * qc];
        ctr[2*nt + 1] = cts[wn * 64 + nt * 8 + 2 * qc + 1];
    }

    uint32_t* selb = (uint32_t*)smem;    // 256 rows x 8 keys = 8KB (A dead)

#pragma unroll
    for (int mt = 0; mt < 4; mt++) {
#pragma unroll
        for (int half = 0; half < 2; half++) {
            uint32_t t0 = ~0u, t1 = ~0u, t2 = ~0u, t3 = ~0u;
#pragma unroll
            for (int nt = 0; nt < 8; nt++) {
#pragma unroll
                for (int e = 0; e < 2; e++) {
                    const int col = wn * 64 + nt * 8 + 2 * qc + e;
                    const float s = ctr[2*nt + e] - 2.f * acc[mt][nt][half * 2 + e];
                    const uint32_t key = (__float_as_uint(s) & 0xFFFFFF80u)
                                       | (uint32_t)col;
                    INS4_U32(key);
                }
            }
            MERGE4_XOR32(1);         // combine qc pairs
            MERGE4_XOR32(2);         // combine qc quads
            if (qc == 0) {
                const int row = wm * 64 + mt * 16 + half * 8 + qr;
                uint32_t* d = selb + row * 8 + wn * 4;
                d[0] = t0; d[1] = t1; d[2] = t2; d[3] = t3;
            }
        }
    }
    __syncthreads();

    // final cross-warp merge: one thread per row, write tile top-4 (uint4)
    if (tid < 256) {
        const uint32_t* s = selb + tid * 8;
        const uint32_t a0 = s[0], a1 = s[1], a2 = s[2], a3 = s[3];
        const uint32_t b0 = s[4], b1 = s[5], b2 = s[6], b3 = s[7];
        const uint32_t l0 = min(a0, b3), l1 = min(a1, b2);
        const uint32_t l2 = min(a2, b1), l3 = min(a3, b0);
        const uint32_t m0 = min(l0, l2), m2 = max(l0, l2);
        const uint32_t m1 = min(l1, l3), m3 = max(l1, l3);
        uint4 o;
        o.x = min(m0, m1); o.y = max(m0, m1);
        o.z = min(m2, m3); o.w = max(m2, m3);
        *(uint4*)(g_cand1 + ((size_t)tid * N_TILES + blockIdx.x) * 4) = o;
    }
}

// ---------------- kernel 2: per-row top-24 from 1564 tile candidates -------
__global__ __launch_bounds__(256) void k_sel()
{
    __shared__ u64 buf[128];
    const int row  = blockIdx.x;
    const int tid  = threadIdx.x;
    const int warp = tid >> 5;
    const int lane = tid & 31;
    const uint32_t* keys = g_cand1 + (size_t)row * (N_TILES * 4);

    // u64 key = (key32 << 32) | position  (position -> uniqueness)
    u64 t0 = ~0ull, t1 = ~0ull, t2 = ~0ull, t3 = ~0ull;
    for (int i = tid; i < N_TILES * 4; i += 256) {
        const u64 k = ((u64)keys[i] << 32) | (unsigned)i;
        INS4_U64(k);
    }

    // warp top-16 extraction (keys unique -> exactly one lane shifts)
    u64 mine = ~0ull;
#pragma unroll
    for (int r = 0; r < 16; r++) {
        u64 k = t0;
#pragma unroll
        for (int o = 16; o > 0; o >>= 1)
            k = umin64(k, __shfl_xor_sync(0xffffffffu, k, o));
        if (lane == r) mine = k;
        if (k == t0) { t0 = t1; t1 = t2; t2 = t3; t3 = ~0ull; }
    }
    if (lane < 16) buf[warp * 16 + lane] = mine;
    __syncthreads();

    // rank-select top-NCAND of 128; decode global index
    if (tid < 128) {
        const u64 v = buf[tid];
        int rk = 0;
        for (int o = 0; o < 128; o++) rk += (buf[o] < v);
        if (rk < NCAND) {
            const uint32_t key32 = (uint32_t)(v >> 32);
            const uint32_t pos   = (uint32_t)(v & 0xffffffffu);
            const int gidx = (int)(pos >> 2) * TILE_N + (int)(key32 & 127u);
            g_cand2[row * NCAND + rk] = gidx;
        }
    }
}

// ---------------- kernel 3: exact rerank + L1 + max -------------------------
// 768 threads = 24 warps: one warp per candidate (single gather pass).
__global__ __launch_bounds__(768) void k_post(
    const float* __restrict__ Xt, const float* __restrict__ X,
    const float* __restrict__ w, float* __restrict__ out)
{
    __shared__ int   cand[NCAND];
    __shared__ float xts[DIM];
    __shared__ float d2s[NCAND];
    __shared__ float acts[NCAND];

    const int row  = blockIdx.x;
    const int tid  = threadIdx.x;
    const int warp = tid >> 5;
    const int lane = tid & 31;

    if (tid < NCAND) cand[tid] = g_cand2[row * NCAND + tid];

    const float4* xtg = (const float4*)(Xt + (size_t)row * DIM);
    for (int i = tid; i < DIM / 4; i += 768) ((float4*)xts)[i] = xtg[i];
    __syncthreads();

    if (warp < NCAND) {
        const int j = cand[warp];
        const float4* xj  = (const float4*)(X + (size_t)j * DIM);
        const float4* xt4 = (const float4*)xts;
        float dot = 0.f, l1 = 0.f;
#pragma unroll 4
        for (int i = lane; i < DIM / 4; i += 32) {
            const float4 a = xj[i], b = xt4[i];
            dot = fmaf(a.x, b.x, fmaf(a.y, b.y, fmaf(a.z, b.z, fmaf(a.w, b.w, dot))));
            l1 += fabsf(a.x-b.x) + fabsf(a.y-b.y) + fabsf(a.z-b.z) + fabsf(a.w-b.w);
        }
#pragma unroll
        for (int o = 16; o > 0; o >>= 1) {
            dot += __shfl_xor_sync(0xffffffffu, dot, o);
            l1  += __shfl_xor_sync(0xffffffffu, l1,  o);
        }
        if (lane == 0) {
            d2s[warp]  = g_ct[j] - 2.f * dot;
            acts[warp] = w[j] - KCONST * l1;
        }
    }
    __syncthreads();

    // exact top-16 by d2 (reference tie-break), max activation among them
    if (tid < 32) {
        const float v = (tid < NCAND) ? d2s[tid] : INF_F;
        const int   j = (tid < NCAND) ? cand[tid] : 0x7fffffff;
        int rank = 0;
#pragma unroll
        for (int o = 0; o < 32; o++) {
            const float ov = __shfl_sync(0xffffffffu, v, o);
            const int   oj = __shfl_sync(0xffffffffu, j, o);
            rank += (ov < v || (ov == v && oj < j)) ? 1 : 0;
        }
        float a = (rank < TOPK && tid < NCAND) ? acts[tid] : -INF_F;
#pragma unroll
        for (int o = 16; o > 0; o >>= 1) a = fmaxf(a, __shfl_xor_sync(0xffffffffu, a, o));
        if (tid == 0) out[row] = a;
    }
}

// ---------------------------------------------------------------------------
extern "C" void kernel_launch(void* const* d_in, const int* in_sizes, int n_in,
                              void* d_out, int out_size)
{
    const float* Xt = (const float*)d_in[0];
    const float* X  = (const float*)d_in[1];
    const float* w  = (const float*)d_in[2];
    float* out = (float*)d_out;

    cudaFuncSetAttribute(k_score, cudaFuncAttributeMaxDynamicSharedMemorySize,
                         SMEM_TOTAL);

    k_cvtw<<<33, 256>>>(Xt, w);
    k_score<<<N_TILES, 256, SMEM_TOTAL>>>(X, w);
    k_sel<<<M_Q, 256>>>();
    k_post<<<M_Q, 768>>>(Xt, X, w, out);
}